// round 2
// baseline (speedup 1.0000x reference)
#include <cuda_runtime.h>
#include <cuda_bf16.h>
#include <cstdint>

// ---------------- problem constants ----------------
#define D_MODEL 1024
#define NHEAD   16
#define D_HEAD  64
#define D_FF    4096
#define BATCH   2
#define SEQ     2048
#define NTOK    (BATCH * SEQ)       // 4096 tokens
#define EPS     1e-5f

// ---------------- scratch (no allocations allowed) ----------------
__device__ float g_q  [NTOK * D_MODEL];
__device__ float g_k  [NTOK * D_MODEL];
__device__ float g_v  [NTOK * D_MODEL];
__device__ float g_att[NTOK * D_MODEL];
__device__ float g_tmp[NTOK * D_MODEL];   // attn_proj, then ffn2 out
__device__ float g_h  [NTOK * D_MODEL];   // LN1 output
__device__ float g_ff [NTOK * D_FF];      // FFN hidden

// =======================================================================
// GEMM: C[M,N] = A[M,K] @ W[N,K]^T + bias[N]   (optional ReLU)
// BM=BN=128, BK=8, 256 threads, 8x8 per-thread microtile.
// All of M,N,K are multiples of 128 here -> no bounds checks.
// =======================================================================
#define BM 128
#define BN 128
#define BK 8
#define TM 8
#define TN 8

template <bool RELU>
__global__ __launch_bounds__(256, 2)
void gemm_bias_kernel(const float* __restrict__ A,
                      const float* __restrict__ W,
                      const float* __restrict__ bias,
                      float* __restrict__ C,
                      int M, int N, int K)
{
    __shared__ float As[BK][BM];
    __shared__ float Ws[BK][BN];

    const int tid = threadIdx.x;
    const int bm  = blockIdx.y * BM;
    const int bn  = blockIdx.x * BN;

    const int tx = tid & 15;        // 0..15 -> N direction
    const int ty = tid >> 4;        // 0..15 -> M direction

    float acc[TM][TN];
#pragma unroll
    for (int i = 0; i < TM; i++)
#pragma unroll
        for (int j = 0; j < TN; j++) acc[i][j] = 0.f;

    // cooperative loads: 256 threads, each one float4 from A-tile and W-tile
    const int lrow = tid >> 1;            // 0..127
    const int lcol = (tid & 1) * 4;       // 0 or 4
    const float* Aptr = A + (size_t)(bm + lrow) * K + lcol;
    const float* Wptr = W + (size_t)(bn + lrow) * K + lcol;

    for (int k0 = 0; k0 < K; k0 += BK) {
        float4 av = *(const float4*)(Aptr + k0);
        float4 wv = *(const float4*)(Wptr + k0);
        As[lcol + 0][lrow] = av.x;
        As[lcol + 1][lrow] = av.y;
        As[lcol + 2][lrow] = av.z;
        As[lcol + 3][lrow] = av.w;
        Ws[lcol + 0][lrow] = wv.x;
        Ws[lcol + 1][lrow] = wv.y;
        Ws[lcol + 2][lrow] = wv.z;
        Ws[lcol + 3][lrow] = wv.w;
        __syncthreads();

#pragma unroll
        for (int kk = 0; kk < BK; kk++) {
            float4 a0 = *(const float4*)&As[kk][ty * TM];
            float4 a1 = *(const float4*)&As[kk][ty * TM + 4];
            float4 w0 = *(const float4*)&Ws[kk][tx * TN];
            float4 w1 = *(const float4*)&Ws[kk][tx * TN + 4];
            float a[TM] = {a0.x, a0.y, a0.z, a0.w, a1.x, a1.y, a1.z, a1.w};
            float w[TN] = {w0.x, w0.y, w0.z, w0.w, w1.x, w1.y, w1.z, w1.w};
#pragma unroll
            for (int i = 0; i < TM; i++)
#pragma unroll
                for (int j = 0; j < TN; j++)
                    acc[i][j] = fmaf(a[i], w[j], acc[i][j]);
        }
        __syncthreads();
    }

    // epilogue
#pragma unroll
    for (int i = 0; i < TM; i++) {
        const int row = bm + ty * TM + i;
        float* crow = C + (size_t)row * N + bn + tx * TN;
#pragma unroll
        for (int j = 0; j < TN; j += 4) {
            float4 o;
            float b0 = bias[bn + tx * TN + j + 0];
            float b1 = bias[bn + tx * TN + j + 1];
            float b2 = bias[bn + tx * TN + j + 2];
            float b3 = bias[bn + tx * TN + j + 3];
            o.x = acc[i][j + 0] + b0;
            o.y = acc[i][j + 1] + b1;
            o.z = acc[i][j + 2] + b2;
            o.w = acc[i][j + 3] + b3;
            if (RELU) {
                o.x = fmaxf(o.x, 0.f); o.y = fmaxf(o.y, 0.f);
                o.z = fmaxf(o.z, 0.f); o.w = fmaxf(o.w, 0.f);
            }
            *(float4*)(crow + j) = o;
        }
    }
}

// =======================================================================
// Flash attention (fp32). Layout of q/k/v buffers: [B*S, D_MODEL] where
// head h of token t occupies columns [h*64, h*64+64).
// Block: 128 threads, each owns ONE query row (O accumulator in regs).
// Grid: (SEQ/128, BATCH*NHEAD).
// =======================================================================
#define AQ 128
#define AK 32

__global__ __launch_bounds__(128, 2)
void flash_attn_kernel(const float* __restrict__ Q,
                       const float* __restrict__ Kb,
                       const float* __restrict__ Vb,
                       float* __restrict__ O)
{
    __shared__ float Qs[AQ][D_HEAD + 1];   // +1 pad: per-thread row reads conflict-free
    __shared__ float Ks[AK][D_HEAD];
    __shared__ float Vs[AK][D_HEAD];

    const int tid = threadIdx.x;           // 0..127
    const int bh  = blockIdx.y;            // b*NHEAD + h
    const int b   = bh / NHEAD;
    const int h   = bh % NHEAD;
    const int q0  = blockIdx.x * AQ;

    const size_t base = (size_t)b * SEQ * D_MODEL + (size_t)h * D_HEAD;

    // load my query row into smem (also warms it for potential re-reads)
    {
        const float* qrow = Q + base + (size_t)(q0 + tid) * D_MODEL;
#pragma unroll
        for (int d = 0; d < D_HEAD; d += 4) {
            float4 v = *(const float4*)(qrow + d);
            Qs[tid][d + 0] = v.x; Qs[tid][d + 1] = v.y;
            Qs[tid][d + 2] = v.z; Qs[tid][d + 3] = v.w;
        }
    }

    float o[D_HEAD];
#pragma unroll
    for (int d = 0; d < D_HEAD; d++) o[d] = 0.f;
    float m = -1e30f, l = 0.f;

    for (int k0 = 0; k0 < SEQ; k0 += AK) {
        __syncthreads();
        // load K,V tile: 32x64 floats = 512 float4 slots, 128 thr * 4 each
#pragma unroll
        for (int i = 0; i < 4; i++) {
            int f = tid + i * 128;          // 0..511
            int r = f >> 4;                 // 0..31
            int c = (f & 15) * 4;           // 0..60
            const size_t src = base + (size_t)(k0 + r) * D_MODEL + c;
            *(float4*)&Ks[r][c] = *(const float4*)(Kb + src);
            *(float4*)&Vs[r][c] = *(const float4*)(Vb + src);
        }
        __syncthreads();

        float s[AK];
#pragma unroll
        for (int j = 0; j < AK; j++) s[j] = 0.f;
#pragma unroll 8
        for (int d = 0; d < D_HEAD; d++) {
            float qv = Qs[tid][d];
#pragma unroll
            for (int j = 0; j < AK; j++)
                s[j] = fmaf(qv, Ks[j][d], s[j]);
        }

        float mt = m;
#pragma unroll
        for (int j = 0; j < AK; j++) {
            s[j] *= 0.125f;                 // 1/sqrt(64)
            mt = fmaxf(mt, s[j]);
        }
        float corr = __expf(m - mt);
        m = mt;
        float ls = 0.f;
#pragma unroll
        for (int j = 0; j < AK; j++) {
            s[j] = __expf(s[j] - mt);
            ls += s[j];
        }
        l = l * corr + ls;

#pragma unroll
        for (int d = 0; d < D_HEAD; d++) o[d] *= corr;
#pragma unroll
        for (int j = 0; j < AK; j++) {
            float p = s[j];
#pragma unroll
            for (int d = 0; d < D_HEAD; d++)
                o[d] = fmaf(p, Vs[j][d], o[d]);
        }
    }

    const float inv = 1.f / l;
    float* orow = O + base + (size_t)(q0 + tid) * D_MODEL;
#pragma unroll
    for (int d = 0; d < D_HEAD; d += 4) {
        float4 v;
        v.x = o[d + 0] * inv; v.y = o[d + 1] * inv;
        v.z = o[d + 2] * inv; v.w = o[d + 3] * inv;
        *(float4*)(orow + d) = v;
    }
}

// =======================================================================
// Fused residual add + LayerNorm: out = LN(X + Y) * g + be
// One block (256 threads) per row of 1024.
// =======================================================================
__device__ __forceinline__ float block_sum(float v, float* red)
{
    for (int o = 16; o; o >>= 1) v += __shfl_down_sync(0xffffffffu, v, o);
    if ((threadIdx.x & 31) == 0) red[threadIdx.x >> 5] = v;
    __syncthreads();
    if (threadIdx.x < 8) {
        v = red[threadIdx.x];
        for (int o = 4; o; o >>= 1) v += __shfl_down_sync(0xffu, v, o);
        if (threadIdx.x == 0) red[0] = v;
    }
    __syncthreads();
    float r = red[0];
    __syncthreads();      // protect red[] for the second reduction
    return r;
}

__global__ __launch_bounds__(256)
void add_ln_kernel(const float* __restrict__ X,
                   const float* __restrict__ Y,
                   const float* __restrict__ g,
                   const float* __restrict__ be,
                   float* __restrict__ out)
{
    __shared__ float red[8];
    const int row = blockIdx.x;
    const int tid = threadIdx.x;
    const float* xr = X + (size_t)row * D_MODEL;
    const float* yr = Y + (size_t)row * D_MODEL;

    float vals[4];
    float sum = 0.f;
#pragma unroll
    for (int i = 0; i < 4; i++) {
        int c = tid + i * 256;
        vals[i] = xr[c] + yr[c];
        sum += vals[i];
    }
    float mu = block_sum(sum, red) * (1.f / D_MODEL);

    float vsum = 0.f;
#pragma unroll
    for (int i = 0; i < 4; i++) {
        float d = vals[i] - mu;
        vsum += d * d;
    }
    float var = block_sum(vsum, red) * (1.f / D_MODEL);
    float rstd = rsqrtf(var + EPS);

    float* orow = out + (size_t)row * D_MODEL;
#pragma unroll
    for (int i = 0; i < 4; i++) {
        int c = tid + i * 256;
        orow[c] = (vals[i] - mu) * rstd * g[c] + be[c];
    }
}

// =======================================================================
// kernel_launch
// input order: x, Wq, bq, Wk, bk, Wv, bv, Wo, bo, W1, b1, W2, b2, g1, be1, g2, be2
// =======================================================================
extern "C" void kernel_launch(void* const* d_in, const int* in_sizes, int n_in,
                              void* d_out, int out_size)
{
    const float* x   = (const float*)d_in[0];
    const float* Wq  = (const float*)d_in[1];
    const float* bq  = (const float*)d_in[2];
    const float* Wk  = (const float*)d_in[3];
    const float* bk  = (const float*)d_in[4];
    const float* Wv  = (const float*)d_in[5];
    const float* bv  = (const float*)d_in[6];
    const float* Wo  = (const float*)d_in[7];
    const float* bo  = (const float*)d_in[8];
    const float* W1  = (const float*)d_in[9];
    const float* b1  = (const float*)d_in[10];
    const float* W2  = (const float*)d_in[11];
    const float* b2  = (const float*)d_in[12];
    const float* g1  = (const float*)d_in[13];
    const float* be1 = (const float*)d_in[14];
    const float* g2  = (const float*)d_in[15];
    const float* be2 = (const float*)d_in[16];
    float* out = (float*)d_out;

    float *q, *k, *v, *att, *tmp, *h, *ff;
    cudaGetSymbolAddress((void**)&q,   g_q);
    cudaGetSymbolAddress((void**)&k,   g_k);
    cudaGetSymbolAddress((void**)&v,   g_v);
    cudaGetSymbolAddress((void**)&att, g_att);
    cudaGetSymbolAddress((void**)&tmp, g_tmp);
    cudaGetSymbolAddress((void**)&h,   g_h);
    cudaGetSymbolAddress((void**)&ff,  g_ff);

    const dim3 gDxD(D_MODEL / BN, NTOK / BM);   // (8, 32)
    const dim3 gFF1(D_FF / BN,    NTOK / BM);   // (32, 32)

    // QKV projections
    gemm_bias_kernel<false><<<gDxD, 256>>>(x, Wq, bq, q, NTOK, D_MODEL, D_MODEL);
    gemm_bias_kernel<false><<<gDxD, 256>>>(x, Wk, bk, k, NTOK, D_MODEL, D_MODEL);
    gemm_bias_kernel<false><<<gDxD, 256>>>(x, Wv, bv, v, NTOK, D_MODEL, D_MODEL);

    // attention
    flash_attn_kernel<<<dim3(SEQ / AQ, BATCH * NHEAD), 128>>>(q, k, v, att);

    // output projection + LN1
    gemm_bias_kernel<false><<<gDxD, 256>>>(att, Wo, bo, tmp, NTOK, D_MODEL, D_MODEL);
    add_ln_kernel<<<NTOK, 256>>>(x, tmp, g1, be1, h);

    // FFN
    gemm_bias_kernel<true ><<<gFF1, 256>>>(h, W1, b1, ff, NTOK, D_FF, D_MODEL);
    gemm_bias_kernel<false><<<gDxD, 256>>>(ff, W2, b2, tmp, NTOK, D_MODEL, D_FF);

    // LN2 -> output
    add_ln_kernel<<<NTOK, 256>>>(h, tmp, g2, be2, out);
}

// round 5
// speedup vs baseline: 1.1001x; 1.1001x over previous
#include <cuda_runtime.h>
#include <cuda_bf16.h>
#include <cstdint>

// ---------------- problem constants ----------------
#define D_MODEL 1024
#define NHEAD   16
#define D_HEAD  64
#define D_FF    4096
#define BATCH   2
#define SEQ     2048
#define NTOK    (BATCH * SEQ)       // 4096 tokens
#define EPS     1e-5f

// ---------------- scratch (no allocations allowed) ----------------
__device__ float g_q  [NTOK * D_MODEL];
__device__ float g_k  [NTOK * D_MODEL];
__device__ float g_v  [NTOK * D_MODEL];
__device__ float g_att[NTOK * D_MODEL];
__device__ float g_tmp[NTOK * D_MODEL];   // attn_proj, then ffn2 out
__device__ float g_h  [NTOK * D_MODEL];   // LN1 output
__device__ float g_ff [NTOK * D_FF];      // FFN hidden

// =======================================================================
// mma.sync tf32 helpers (legacy HMMA path — works with plain sm_103 target)
// =======================================================================
__device__ __forceinline__ uint32_t f32_to_tf32(float x) {
    uint32_t u;
    asm("cvt.rna.tf32.f32 %0, %1;" : "=r"(u) : "f"(x));
    return u;
}

__device__ __forceinline__ void mma_tf32_16x8x8(float* d, const uint32_t* a, const uint32_t* b) {
    asm volatile(
        "mma.sync.aligned.m16n8k8.row.col.f32.tf32.tf32.f32 "
        "{%0,%1,%2,%3}, {%4,%5,%6,%7}, {%8,%9}, {%0,%1,%2,%3};"
        : "+f"(d[0]), "+f"(d[1]), "+f"(d[2]), "+f"(d[3])
        : "r"(a[0]), "r"(a[1]), "r"(a[2]), "r"(a[3]), "r"(b[0]), "r"(b[1]));
}

// =======================================================================
// Tensor-core GEMM (HMMA tf32): C[M,N] = A[M,K] @ W[N,K]^T + bias[N]
// optional ReLU. CTA tile 128x128, BK=16, 256 threads (8 warps, 2x4).
// SMEM rows padded to 20 floats -> conflict-free fragment LDS
// (bank = (g*20 + t4) mod 32 covers all 32 banks).
// Double-buffered with register staging: LDG(t+1) overlaps MMA(t).
// =======================================================================
#define BKC  16
#define LDSW 20

template <bool RELU>
__global__ __launch_bounds__(256, 2)
void gemm_hmma(const float* __restrict__ A, const float* __restrict__ W,
               const float* __restrict__ bias, float* __restrict__ C,
               int M, int N, int K)
{
    __shared__ uint32_t As[2][128 * LDSW];
    __shared__ uint32_t Ws[2][128 * LDSW];

    const int tid  = threadIdx.x;
    const int wid  = tid >> 5;
    const int lane = tid & 31;
    const int wm   = wid & 1;          // 0..1 -> 64 M-rows each
    const int wn   = wid >> 1;         // 0..3 -> 32 N-cols each
    const int g    = lane >> 2;        // groupID (0..7)
    const int t4   = lane & 3;         // thread-in-group (0..3)

    const int bm = blockIdx.y * 128;
    const int bn = blockIdx.x * 128;

    float acc[4][4][4];
#pragma unroll
    for (int i = 0; i < 4; i++)
#pragma unroll
        for (int j = 0; j < 4; j++)
#pragma unroll
            for (int c = 0; c < 4; c++) acc[i][j][c] = 0.f;

    // load slots: 2 per thread per matrix; slot = tid + s*256 (0..511)
    int lrow[2], lc4[2];
#pragma unroll
    for (int s = 0; s < 2; s++) {
        int slot = tid + s * 256;
        lrow[s] = slot >> 2;           // 0..127
        lc4[s]  = (slot & 3) * 4;      // 0,4,8,12 (float offset in chunk)
    }

    const int NT = K / BKC;
    uint4 ra[2], rw[2];

#define LDG_CVT(t)                                                               \
    do {                                                                         \
        _Pragma("unroll")                                                        \
        for (int s = 0; s < 2; s++) {                                            \
            const float4 av = *(const float4*)(A + (size_t)(bm + lrow[s]) * K + (t) * BKC + lc4[s]); \
            const float4 wv = *(const float4*)(W + (size_t)(bn + lrow[s]) * K + (t) * BKC + lc4[s]); \
            ra[s].x = f32_to_tf32(av.x); ra[s].y = f32_to_tf32(av.y);            \
            ra[s].z = f32_to_tf32(av.z); ra[s].w = f32_to_tf32(av.w);            \
            rw[s].x = f32_to_tf32(wv.x); rw[s].y = f32_to_tf32(wv.y);            \
            rw[s].z = f32_to_tf32(wv.z); rw[s].w = f32_to_tf32(wv.w);            \
        }                                                                        \
    } while (0)

#define STS_TILE(buf)                                                            \
    do {                                                                         \
        _Pragma("unroll")                                                        \
        for (int s = 0; s < 2; s++) {                                            \
            *(uint4*)&As[buf][lrow[s] * LDSW + lc4[s]] = ra[s];                  \
            *(uint4*)&Ws[buf][lrow[s] * LDSW + lc4[s]] = rw[s];                  \
        }                                                                        \
    } while (0)

    // ---- prologue ----
    LDG_CVT(0);
    STS_TILE(0);
    __syncthreads();

    for (int t = 0; t < NT; ++t) {
        const int cur = t & 1;
        if (t + 1 < NT) LDG_CVT(t + 1);     // global latency hides under MMAs

        const uint32_t* as = &As[cur][0];
        const uint32_t* ws = &Ws[cur][0];
#pragma unroll
        for (int ks = 0; ks < 2; ks++) {
            const int k = ks * 8;
            uint32_t af[4][4], bf[4][2];
#pragma unroll
            for (int i = 0; i < 4; i++) {
                const int m = wm * 64 + i * 16;
                af[i][0] = as[(m + g    ) * LDSW + k + t4    ];
                af[i][1] = as[(m + g + 8) * LDSW + k + t4    ];
                af[i][2] = as[(m + g    ) * LDSW + k + t4 + 4];
                af[i][3] = as[(m + g + 8) * LDSW + k + t4 + 4];
            }
#pragma unroll
            for (int j = 0; j < 4; j++) {
                const int n = wn * 32 + j * 8;
                bf[j][0] = ws[(n + g) * LDSW + k + t4    ];
                bf[j][1] = ws[(n + g) * LDSW + k + t4 + 4];
            }
#pragma unroll
            for (int i = 0; i < 4; i++)
#pragma unroll
                for (int j = 0; j < 4; j++)
                    mma_tf32_16x8x8(acc[i][j], af[i], bf[j]);
        }

        if (t + 1 < NT) {
            __syncthreads();                // everyone done reading buf (t+1)&1
            STS_TILE((t + 1) & 1);
            __syncthreads();
        }
    }

    // ---- epilogue: bias (+ReLU), float2 stores ----
#pragma unroll
    for (int j = 0; j < 4; j++) {
        const int col = bn + wn * 32 + j * 8 + t4 * 2;
        const float b0 = bias[col];
        const float b1 = bias[col + 1];
#pragma unroll
        for (int i = 0; i < 4; i++) {
            const int r0 = bm + wm * 64 + i * 16 + g;
            float2 v0, v1;
            v0.x = acc[i][j][0] + b0;  v0.y = acc[i][j][1] + b1;
            v1.x = acc[i][j][2] + b0;  v1.y = acc[i][j][3] + b1;
            if (RELU) {
                v0.x = fmaxf(v0.x, 0.f); v0.y = fmaxf(v0.y, 0.f);
                v1.x = fmaxf(v1.x, 0.f); v1.y = fmaxf(v1.y, 0.f);
            }
            *(float2*)(C + (size_t)r0 * N + col)       = v0;
            *(float2*)(C + (size_t)(r0 + 8) * N + col) = v1;
        }
    }
#undef LDG_CVT
#undef STS_TILE
}

// =======================================================================
// Flash attention (fp32) — unchanged from the passing R1 kernel.
// =======================================================================
#define AQ 128
#define AK 32

__global__ __launch_bounds__(128, 2)
void flash_attn_kernel(const float* __restrict__ Q,
                       const float* __restrict__ Kb,
                       const float* __restrict__ Vb,
                       float* __restrict__ O)
{
    __shared__ float Qs[AQ][D_HEAD + 1];
    __shared__ float Ks[AK][D_HEAD];
    __shared__ float Vs[AK][D_HEAD];

    const int tid = threadIdx.x;
    const int bh  = blockIdx.y;
    const int b   = bh / NHEAD;
    const int h   = bh % NHEAD;
    const int q0  = blockIdx.x * AQ;

    const size_t base = (size_t)b * SEQ * D_MODEL + (size_t)h * D_HEAD;

    {
        const float* qrow = Q + base + (size_t)(q0 + tid) * D_MODEL;
#pragma unroll
        for (int d = 0; d < D_HEAD; d += 4) {
            float4 v = *(const float4*)(qrow + d);
            Qs[tid][d + 0] = v.x; Qs[tid][d + 1] = v.y;
            Qs[tid][d + 2] = v.z; Qs[tid][d + 3] = v.w;
        }
    }

    float o[D_HEAD];
#pragma unroll
    for (int d = 0; d < D_HEAD; d++) o[d] = 0.f;
    float m = -1e30f, l = 0.f;

    for (int k0 = 0; k0 < SEQ; k0 += AK) {
        __syncthreads();
#pragma unroll
        for (int i = 0; i < 4; i++) {
            int f = tid + i * 128;
            int r = f >> 4;
            int c = (f & 15) * 4;
            const size_t src = base + (size_t)(k0 + r) * D_MODEL + c;
            *(float4*)&Ks[r][c] = *(const float4*)(Kb + src);
            *(float4*)&Vs[r][c] = *(const float4*)(Vb + src);
        }
        __syncthreads();

        float s[AK];
#pragma unroll
        for (int j = 0; j < AK; j++) s[j] = 0.f;
#pragma unroll 8
        for (int d = 0; d < D_HEAD; d++) {
            float qv = Qs[tid][d];
#pragma unroll
            for (int j = 0; j < AK; j++)
                s[j] = fmaf(qv, Ks[j][d], s[j]);
        }

        float mt = m;
#pragma unroll
        for (int j = 0; j < AK; j++) {
            s[j] *= 0.125f;
            mt = fmaxf(mt, s[j]);
        }
        float corr = __expf(m - mt);
        m = mt;
        float ls = 0.f;
#pragma unroll
        for (int j = 0; j < AK; j++) {
            s[j] = __expf(s[j] - mt);
            ls += s[j];
        }
        l = l * corr + ls;

#pragma unroll
        for (int d = 0; d < D_HEAD; d++) o[d] *= corr;
#pragma unroll
        for (int j = 0; j < AK; j++) {
            float p = s[j];
#pragma unroll
            for (int d = 0; d < D_HEAD; d++)
                o[d] = fmaf(p, Vs[j][d], o[d]);
        }
    }

    const float inv = 1.f / l;
    float* orow = O + base + (size_t)(q0 + tid) * D_MODEL;
#pragma unroll
    for (int d = 0; d < D_HEAD; d += 4) {
        float4 v;
        v.x = o[d + 0] * inv; v.y = o[d + 1] * inv;
        v.z = o[d + 2] * inv; v.w = o[d + 3] * inv;
        *(float4*)(orow + d) = v;
    }
}

// =======================================================================
// Fused residual add + LayerNorm — unchanged.
// =======================================================================
__device__ __forceinline__ float block_sum(float v, float* red)
{
    for (int o = 16; o; o >>= 1) v += __shfl_down_sync(0xffffffffu, v, o);
    if ((threadIdx.x & 31) == 0) red[threadIdx.x >> 5] = v;
    __syncthreads();
    if (threadIdx.x < 8) {
        v = red[threadIdx.x];
        for (int o = 4; o; o >>= 1) v += __shfl_down_sync(0xffu, v, o);
        if (threadIdx.x == 0) red[0] = v;
    }
    __syncthreads();
    float r = red[0];
    __syncthreads();
    return r;
}

__global__ __launch_bounds__(256)
void add_ln_kernel(const float* __restrict__ X,
                   const float* __restrict__ Y,
                   const float* __restrict__ g,
                   const float* __restrict__ be,
                   float* __restrict__ out)
{
    __shared__ float red[8];
    const int row = blockIdx.x;
    const int tid = threadIdx.x;
    const float* xr = X + (size_t)row * D_MODEL;
    const float* yr = Y + (size_t)row * D_MODEL;

    float vals[4];
    float sum = 0.f;
#pragma unroll
    for (int i = 0; i < 4; i++) {
        int c = tid + i * 256;
        vals[i] = xr[c] + yr[c];
        sum += vals[i];
    }
    float mu = block_sum(sum, red) * (1.f / D_MODEL);

    float vsum = 0.f;
#pragma unroll
    for (int i = 0; i < 4; i++) {
        float d = vals[i] - mu;
        vsum += d * d;
    }
    float var = block_sum(vsum, red) * (1.f / D_MODEL);
    float rstd = rsqrtf(var + EPS);

    float* orow = out + (size_t)row * D_MODEL;
#pragma unroll
    for (int i = 0; i < 4; i++) {
        int c = tid + i * 256;
        orow[c] = (vals[i] - mu) * rstd * g[c] + be[c];
    }
}

// =======================================================================
// kernel_launch
// input order: x, Wq, bq, Wk, bk, Wv, bv, Wo, bo, W1, b1, W2, b2, g1, be1, g2, be2
// =======================================================================
extern "C" void kernel_launch(void* const* d_in, const int* in_sizes, int n_in,
                              void* d_out, int out_size)
{
    const float* x   = (const float*)d_in[0];
    const float* Wq  = (const float*)d_in[1];
    const float* bq  = (const float*)d_in[2];
    const float* Wk  = (const float*)d_in[3];
    const float* bk  = (const float*)d_in[4];
    const float* Wv  = (const float*)d_in[5];
    const float* bv  = (const float*)d_in[6];
    const float* Wo  = (const float*)d_in[7];
    const float* bo  = (const float*)d_in[8];
    const float* W1  = (const float*)d_in[9];
    const float* b1  = (const float*)d_in[10];
    const float* W2  = (const float*)d_in[11];
    const float* b2  = (const float*)d_in[12];
    const float* g1  = (const float*)d_in[13];
    const float* be1 = (const float*)d_in[14];
    const float* g2  = (const float*)d_in[15];
    const float* be2 = (const float*)d_in[16];
    float* out = (float*)d_out;

    float *q, *k, *v, *att, *tmp, *h, *ff;
    cudaGetSymbolAddress((void**)&q,   g_q);
    cudaGetSymbolAddress((void**)&k,   g_k);
    cudaGetSymbolAddress((void**)&v,   g_v);
    cudaGetSymbolAddress((void**)&att, g_att);
    cudaGetSymbolAddress((void**)&tmp, g_tmp);
    cudaGetSymbolAddress((void**)&h,   g_h);
    cudaGetSymbolAddress((void**)&ff,  g_ff);

    const dim3 gDxD(D_MODEL / 128, NTOK / 128);   // (8, 32)
    const dim3 gFF1(D_FF / 128,    NTOK / 128);   // (32, 32)

    // QKV projections (HMMA tf32)
    gemm_hmma<false><<<gDxD, 256>>>(x, Wq, bq, q, NTOK, D_MODEL, D_MODEL);
    gemm_hmma<false><<<gDxD, 256>>>(x, Wk, bk, k, NTOK, D_MODEL, D_MODEL);
    gemm_hmma<false><<<gDxD, 256>>>(x, Wv, bv, v, NTOK, D_MODEL, D_MODEL);

    // attention
    flash_attn_kernel<<<dim3(SEQ / AQ, BATCH * NHEAD), 128>>>(q, k, v, att);

    // output projection + LN1
    gemm_hmma<false><<<gDxD, 256>>>(att, Wo, bo, tmp, NTOK, D_MODEL, D_MODEL);
    add_ln_kernel<<<NTOK, 256>>>(x, tmp, g1, be1, h);

    // FFN
    gemm_hmma<true ><<<gFF1, 256>>>(h, W1, b1, ff, NTOK, D_FF, D_MODEL);
    gemm_hmma<false><<<gDxD, 256>>>(ff, W2, b2, tmp, NTOK, D_MODEL, D_FF);

    // LN2 -> output
    add_ln_kernel<<<NTOK, 256>>>(h, tmp, g2, be2, out);
}

// round 6
// speedup vs baseline: 5.5783x; 5.0705x over previous
#include <cuda_runtime.h>
#include <cuda_fp16.h>
#include <cuda_bf16.h>
#include <cstdint>

// ---------------- problem constants ----------------
#define D_MODEL 1024
#define NHEAD   16
#define D_HEAD  64
#define D_FF    4096
#define BATCH   2
#define SEQ     2048
#define NTOK    (BATCH * SEQ)       // 4096 tokens
#define EPS     1e-5f

// ---------------- scratch (no allocations allowed) ----------------
__device__ __half g_qh [NTOK * D_MODEL];
__device__ __half g_kh [NTOK * D_MODEL];
__device__ __half g_vh [NTOK * D_MODEL];
__device__ float  g_att[NTOK * D_MODEL];
__device__ float  g_tmp[NTOK * D_MODEL];   // attn_proj, then ffn2 out
__device__ float  g_h  [NTOK * D_MODEL];   // LN1 output
__device__ float  g_ff [NTOK * D_FF];      // FFN hidden

// =======================================================================
// PTX helpers (plain sm_103-compatible: mma.sync / ldmatrix / cp.async)
// =======================================================================
__device__ __forceinline__ uint32_t smem_u32(const void* p) {
    uint32_t a;
    asm("{ .reg .u64 t; cvta.to.shared.u64 t, %1; cvt.u32.u64 %0, t; }"
        : "=r"(a) : "l"(p));
    return a;
}

__device__ __forceinline__ void mma16816(float* d, const uint32_t* a, const uint32_t* b) {
    asm volatile(
        "mma.sync.aligned.m16n8k16.row.col.f32.f16.f16.f32 "
        "{%0,%1,%2,%3}, {%4,%5,%6,%7}, {%8,%9}, {%0,%1,%2,%3};"
        : "+f"(d[0]), "+f"(d[1]), "+f"(d[2]), "+f"(d[3])
        : "r"(a[0]), "r"(a[1]), "r"(a[2]), "r"(a[3]), "r"(b[0]), "r"(b[1]));
}

#define LDMX4(r0, r1, r2, r3, addr)                                         \
    asm volatile("ldmatrix.sync.aligned.m8n8.x4.shared.b16 "                \
                 "{%0,%1,%2,%3}, [%4];"                                     \
                 : "=r"(r0), "=r"(r1), "=r"(r2), "=r"(r3) : "r"(addr))

#define LDMX4T(r0, r1, r2, r3, addr)                                        \
    asm volatile("ldmatrix.sync.aligned.m8n8.x4.trans.shared.b16 "          \
                 "{%0,%1,%2,%3}, [%4];"                                     \
                 : "=r"(r0), "=r"(r1), "=r"(r2), "=r"(r3) : "r"(addr))

#define CP_ASYNC16(saddr, gaddr)                                            \
    asm volatile("cp.async.cg.shared.global [%0], [%1], 16;"                \
                 :: "r"(saddr), "l"(gaddr) : "memory")
#define CP_COMMIT() asm volatile("cp.async.commit_group;" ::: "memory")
#define CP_WAIT(n)  asm volatile("cp.async.wait_group %0;" :: "n"(n) : "memory")

__device__ __forceinline__ uint32_t pack_h2(float lo, float hi) {
    __half2 h = __float22half2_rn(make_float2(lo, hi));
    return *(uint32_t*)&h;
}

// =======================================================================
// fp16 HMMA GEMM: C[M,N] = A[M,K] @ W[N,K]^T + bias[N]
// A,W fp32 in gmem -> cvt fp16 at load. Optional ReLU, optional half output.
// CTA 128x128, BK=32, 256 threads = 8 warps (2 M x 4 N), warp tile 64x32.
// SMEM rows padded to 40 halfs (80B): ldmatrix row shift = 20 banks ->
// 8 rows cover all 32 banks, conflict-free.
// =======================================================================
#define LDSH 40        // padded row stride in halfs (32 + 8)

template <bool RELU, bool HALF_OUT>
__global__ __launch_bounds__(256, 2)
void gemm_h(const float* __restrict__ A, const float* __restrict__ W,
            const float* __restrict__ bias, void* __restrict__ Cout,
            int M, int N, int K)
{
    __shared__ __half As[2][128 * LDSH];
    __shared__ __half Ws[2][128 * LDSH];

    const int tid  = threadIdx.x;
    const int wid  = tid >> 5;
    const int lane = tid & 31;
    const int wm   = wid & 1;          // 2 -> 64 M-rows
    const int wn   = wid >> 1;         // 4 -> 32 N-cols
    const int g    = lane >> 2;
    const int t4   = lane & 3;

    const int bm = blockIdx.y * 128;
    const int bn = blockIdx.x * 128;

    float acc[4][4][4];
#pragma unroll
    for (int i = 0; i < 4; i++)
#pragma unroll
        for (int j = 0; j < 4; j++)
#pragma unroll
            for (int c = 0; c < 4; c++) acc[i][j][c] = 0.f;

    // cooperative load slots: 1024 float4 per matrix per tile, 4 per thread
    int lrow[4], lc4[4];
#pragma unroll
    for (int s = 0; s < 4; s++) {
        int slot = tid + s * 256;
        lrow[s] = slot >> 3;           // 0..127
        lc4[s]  = (slot & 7) * 4;      // float col 0,4,..,28
    }

    // ldmatrix byte offsets (within one buffer)
    const int r7   = lane & 7;
    const int rsel = (lane >> 3) & 1;
    const int hsel = lane >> 4;
    const uint32_t offA0 = (uint32_t)((wm * 64 + r7 + rsel * 8) * (LDSH * 2) + hsel * 16);
    const uint32_t offB0 = (uint32_t)((wn * 32 + r7 + hsel * 8) * (LDSH * 2) + rsel * 16);
    const uint32_t aBase[2] = { smem_u32(As[0]), smem_u32(As[1]) };
    const uint32_t bBase[2] = { smem_u32(Ws[0]), smem_u32(Ws[1]) };

    const int NT = K / 32;
    uint2 ra[4], rw[4];                // staged fp16x4 per slot

#define LDG_CVT(t)                                                              \
    do {                                                                        \
        _Pragma("unroll")                                                       \
        for (int s = 0; s < 4; s++) {                                           \
            const float4 av = *(const float4*)(A + (size_t)(bm + lrow[s]) * K + (t) * 32 + lc4[s]); \
            const float4 wv = *(const float4*)(W + (size_t)(bn + lrow[s]) * K + (t) * 32 + lc4[s]); \
            ra[s].x = pack_h2(av.x, av.y);  ra[s].y = pack_h2(av.z, av.w);      \
            rw[s].x = pack_h2(wv.x, wv.y);  rw[s].y = pack_h2(wv.z, wv.w);      \
        }                                                                       \
    } while (0)

#define STS_TILE(buf)                                                           \
    do {                                                                        \
        _Pragma("unroll")                                                       \
        for (int s = 0; s < 4; s++) {                                           \
            *(uint2*)&As[buf][lrow[s] * LDSH + lc4[s]] = ra[s];                 \
            *(uint2*)&Ws[buf][lrow[s] * LDSH + lc4[s]] = rw[s];                 \
        }                                                                       \
    } while (0)

    LDG_CVT(0);
    STS_TILE(0);
    __syncthreads();

    for (int t = 0; t < NT; ++t) {
        const int cur = t & 1;
        if (t + 1 < NT) LDG_CVT(t + 1);    // hides global latency under MMAs

        const uint32_t ab = aBase[cur] + offA0;
        const uint32_t bb = bBase[cur] + offB0;
#pragma unroll
        for (int ks = 0; ks < 2; ks++) {
            uint32_t af[4][4], bf[4][2];
#pragma unroll
            for (int i = 0; i < 4; i++)
                LDMX4(af[i][0], af[i][1], af[i][2], af[i][3],
                      ab + (uint32_t)(i * 16 * LDSH * 2 + ks * 32));
#pragma unroll
            for (int jp = 0; jp < 2; jp++)
                LDMX4(bf[2 * jp][0], bf[2 * jp][1], bf[2 * jp + 1][0], bf[2 * jp + 1][1],
                      bb + (uint32_t)(jp * 16 * LDSH * 2 + ks * 32));
#pragma unroll
            for (int i = 0; i < 4; i++)
#pragma unroll
                for (int j = 0; j < 4; j++)
                    mma16816(acc[i][j], af[i], bf[j]);
        }

        if (t + 1 < NT) {
            __syncthreads();
            STS_TILE((t + 1) & 1);
            __syncthreads();
        }
    }

    // ---- epilogue ----
#pragma unroll
    for (int j = 0; j < 4; j++) {
        const int col = bn + wn * 32 + j * 8 + t4 * 2;
        const float b0 = bias[col];
        const float b1 = bias[col + 1];
#pragma unroll
        for (int i = 0; i < 4; i++) {
            const int r0 = bm + wm * 64 + i * 16 + g;
            float v00 = acc[i][j][0] + b0, v01 = acc[i][j][1] + b1;
            float v10 = acc[i][j][2] + b0, v11 = acc[i][j][3] + b1;
            if (RELU) {
                v00 = fmaxf(v00, 0.f); v01 = fmaxf(v01, 0.f);
                v10 = fmaxf(v10, 0.f); v11 = fmaxf(v11, 0.f);
            }
            if (HALF_OUT) {
                __half* C = (__half*)Cout;
                *(__half2*)(C + (size_t)r0 * N + col)       = __float22half2_rn(make_float2(v00, v01));
                *(__half2*)(C + (size_t)(r0 + 8) * N + col) = __float22half2_rn(make_float2(v10, v11));
            } else {
                float* C = (float*)Cout;
                *(float2*)(C + (size_t)r0 * N + col)       = make_float2(v00, v01);
                *(float2*)(C + (size_t)(r0 + 8) * N + col) = make_float2(v10, v11);
            }
        }
    }
#undef LDG_CVT
#undef STS_TILE
}

// =======================================================================
// fp16 HMMA flash attention.
// q/k/v: __half [NTOK][D_MODEL], head h in cols [h*64, h*64+64).
// CTA: 128 threads (4 warps), 64 q-rows (warp -> m16 tile).
// K/V: 64-key tiles, cp.async double buffered. Q frags live in registers.
// Online softmax in register fragments (FA2 layout), P repacked in regs.
// Output att: fp32.
// =======================================================================
#define ATS 72         // padded row stride in halfs (64 + 8)

__global__ __launch_bounds__(128)
void flash16(const __half* __restrict__ Q, const __half* __restrict__ Kb,
             const __half* __restrict__ Vb, float* __restrict__ O)
{
    __shared__ __half Qs[64 * ATS];
    __shared__ __half Ks[2][64 * ATS];
    __shared__ __half Vs[2][64 * ATS];

    const int tid  = threadIdx.x;
    const int w    = tid >> 5;
    const int lane = tid & 31;
    const int g    = lane >> 2;
    const int t4   = lane & 3;
    const int bh   = blockIdx.y;
    const int b    = bh >> 4;
    const int h    = bh & 15;
    const int q0   = blockIdx.x * 64;
    const int m    = w * 16;

    const size_t base = (size_t)b * SEQ * D_MODEL + (size_t)h * D_HEAD;

    // ---- load Q tile to smem (64x64 halfs), then fragments to regs ----
#pragma unroll
    for (int s = 0; s < 4; s++) {
        int slot = tid + s * 128;          // 0..511
        int row  = slot >> 3;
        int c8   = (slot & 7) * 8;
        *(uint4*)&Qs[row * ATS + c8] =
            *(const uint4*)(Q + base + (size_t)(q0 + row) * D_MODEL + c8);
    }
    __syncthreads();

    const int r7   = lane & 7;
    const int rsel = (lane >> 3) & 1;
    const int hsel = lane >> 4;

    uint32_t qf[4][4];
    {
        const uint32_t qb = smem_u32(Qs) +
            (uint32_t)((m + r7 + rsel * 8) * (ATS * 2) + hsel * 16);
#pragma unroll
        for (int ks = 0; ks < 4; ks++)
            LDMX4(qf[ks][0], qf[ks][1], qf[ks][2], qf[ks][3], qb + ks * 32);
    }

    // ldmatrix offsets into K/V buffers
    const uint32_t offK0 = (uint32_t)((r7 + hsel * 8) * (ATS * 2) + rsel * 16);
    const uint32_t offV0 = (uint32_t)((rsel * 8 + r7) * (ATS * 2) + hsel * 16);
    const uint32_t kBase[2] = { smem_u32(Ks[0]), smem_u32(Ks[1]) };
    const uint32_t vBase[2] = { smem_u32(Vs[0]), smem_u32(Vs[1]) };

    // cp.async tile loader (one commit group = K tile + V tile)
#define ISSUE_TILE(kt, buf)                                                     \
    do {                                                                        \
        _Pragma("unroll")                                                       \
        for (int s = 0; s < 4; s++) {                                           \
            int slot = tid + s * 128;                                           \
            int row  = slot >> 3;                                               \
            int c8   = (slot & 7) * 8;                                          \
            const size_t go = base + (size_t)((kt) * 64 + row) * D_MODEL + c8;  \
            uint32_t so = (uint32_t)((row * ATS + c8) * 2);                     \
            CP_ASYNC16(kBase[buf] + so, Kb + go);                               \
            CP_ASYNC16(vBase[buf] + so, Vb + go);                               \
        }                                                                       \
        CP_COMMIT();                                                            \
    } while (0)

    float o[8][4];
#pragma unroll
    for (int j = 0; j < 8; j++)
#pragma unroll
        for (int c = 0; c < 4; c++) o[j][c] = 0.f;
    float m0 = -1e30f, m1 = -1e30f, l0 = 0.f, l1 = 0.f;

    ISSUE_TILE(0, 0);

    const int NKT = SEQ / 64;          // 32
    for (int kt = 0; kt < NKT; ++kt) {
        const int buf = kt & 1;
        if (kt + 1 < NKT) { ISSUE_TILE(kt + 1, buf ^ 1); CP_WAIT(1); }
        else              { CP_WAIT(0); }
        __syncthreads();

        // ---- S = Q K^T (m16 x n64, k64) ----
        float s_[8][4];
#pragma unroll
        for (int j = 0; j < 8; j++)
#pragma unroll
            for (int c = 0; c < 4; c++) s_[j][c] = 0.f;

        const uint32_t kb = kBase[buf] + offK0;
#pragma unroll
        for (int ks = 0; ks < 4; ks++) {
            uint32_t bfk[8][2];
#pragma unroll
            for (int jp = 0; jp < 4; jp++)
                LDMX4(bfk[2 * jp][0], bfk[2 * jp][1], bfk[2 * jp + 1][0], bfk[2 * jp + 1][1],
                      kb + (uint32_t)(jp * 16 * ATS * 2 + ks * 32));
#pragma unroll
            for (int j = 0; j < 8; j++)
                mma16816(s_[j], qf[ks], bfk[j]);
        }

        // ---- online softmax (rows g and g+8) ----
        float mx0 = -1e30f, mx1 = -1e30f;
#pragma unroll
        for (int j = 0; j < 8; j++) {
            s_[j][0] *= 0.125f; s_[j][1] *= 0.125f;
            s_[j][2] *= 0.125f; s_[j][3] *= 0.125f;
            mx0 = fmaxf(mx0, fmaxf(s_[j][0], s_[j][1]));
            mx1 = fmaxf(mx1, fmaxf(s_[j][2], s_[j][3]));
        }
        mx0 = fmaxf(mx0, __shfl_xor_sync(0xffffffffu, mx0, 1));
        mx0 = fmaxf(mx0, __shfl_xor_sync(0xffffffffu, mx0, 2));
        mx1 = fmaxf(mx1, __shfl_xor_sync(0xffffffffu, mx1, 1));
        mx1 = fmaxf(mx1, __shfl_xor_sync(0xffffffffu, mx1, 2));

        const float nm0 = fmaxf(m0, mx0);
        const float nm1 = fmaxf(m1, mx1);
        const float cr0 = __expf(m0 - nm0);
        const float cr1 = __expf(m1 - nm1);
        m0 = nm0; m1 = nm1;

        float ps0 = 0.f, ps1 = 0.f;
#pragma unroll
        for (int j = 0; j < 8; j++) {
            s_[j][0] = __expf(s_[j][0] - m0);
            s_[j][1] = __expf(s_[j][1] - m0);
            s_[j][2] = __expf(s_[j][2] - m1);
            s_[j][3] = __expf(s_[j][3] - m1);
            ps0 += s_[j][0] + s_[j][1];
            ps1 += s_[j][2] + s_[j][3];
        }
        ps0 += __shfl_xor_sync(0xffffffffu, ps0, 1);
        ps0 += __shfl_xor_sync(0xffffffffu, ps0, 2);
        ps1 += __shfl_xor_sync(0xffffffffu, ps1, 1);
        ps1 += __shfl_xor_sync(0xffffffffu, ps1, 2);
        l0 = l0 * cr0 + ps0;
        l1 = l1 * cr1 + ps1;

#pragma unroll
        for (int j = 0; j < 8; j++) {
            o[j][0] *= cr0; o[j][1] *= cr0;
            o[j][2] *= cr1; o[j][3] *= cr1;
        }

        // ---- O += P V  (P repacked as A-frags from S frags) ----
        const uint32_t vb = vBase[buf] + offV0;
#pragma unroll
        for (int ks = 0; ks < 4; ks++) {
            uint32_t pa[4];
            pa[0] = pack_h2(s_[2 * ks][0],     s_[2 * ks][1]);
            pa[1] = pack_h2(s_[2 * ks][2],     s_[2 * ks][3]);
            pa[2] = pack_h2(s_[2 * ks + 1][0], s_[2 * ks + 1][1]);
            pa[3] = pack_h2(s_[2 * ks + 1][2], s_[2 * ks + 1][3]);

            uint32_t bfv[8][2];
#pragma unroll
            for (int jp = 0; jp < 4; jp++)
                LDMX4T(bfv[2 * jp][0], bfv[2 * jp][1], bfv[2 * jp + 1][0], bfv[2 * jp + 1][1],
                       vb + (uint32_t)(ks * 16 * ATS * 2 + jp * 32));
#pragma unroll
            for (int j = 0; j < 8; j++)
                mma16816(o[j], pa, bfv[j]);
        }
        __syncthreads();
    }

    // ---- finalize + store (fp32) ----
    const float inv0 = 1.f / l0;
    const float inv1 = 1.f / l1;
    const int row0 = q0 + m + g;
    const int row1 = row0 + 8;
#pragma unroll
    for (int j = 0; j < 8; j++) {
        const int col = j * 8 + t4 * 2;
        *(float2*)(O + base + (size_t)row0 * D_MODEL + col) =
            make_float2(o[j][0] * inv0, o[j][1] * inv0);
        *(float2*)(O + base + (size_t)row1 * D_MODEL + col) =
            make_float2(o[j][2] * inv1, o[j][3] * inv1);
    }
#undef ISSUE_TILE
}

// =======================================================================
// Fused residual add + LayerNorm — unchanged.
// =======================================================================
__device__ __forceinline__ float block_sum(float v, float* red)
{
    for (int o = 16; o; o >>= 1) v += __shfl_down_sync(0xffffffffu, v, o);
    if ((threadIdx.x & 31) == 0) red[threadIdx.x >> 5] = v;
    __syncthreads();
    if (threadIdx.x < 8) {
        v = red[threadIdx.x];
        for (int o = 4; o; o >>= 1) v += __shfl_down_sync(0xffu, v, o);
        if (threadIdx.x == 0) red[0] = v;
    }
    __syncthreads();
    float r = red[0];
    __syncthreads();
    return r;
}

__global__ __launch_bounds__(256)
void add_ln_kernel(const float* __restrict__ X,
                   const float* __restrict__ Y,
                   const float* __restrict__ g,
                   const float* __restrict__ be,
                   float* __restrict__ out)
{
    __shared__ float red[8];
    const int row = blockIdx.x;
    const int tid = threadIdx.x;
    const float* xr = X + (size_t)row * D_MODEL;
    const float* yr = Y + (size_t)row * D_MODEL;

    float vals[4];
    float sum = 0.f;
#pragma unroll
    for (int i = 0; i < 4; i++) {
        int c = tid + i * 256;
        vals[i] = xr[c] + yr[c];
        sum += vals[i];
    }
    float mu = block_sum(sum, red) * (1.f / D_MODEL);

    float vsum = 0.f;
#pragma unroll
    for (int i = 0; i < 4; i++) {
        float d = vals[i] - mu;
        vsum += d * d;
    }
    float var = block_sum(vsum, red) * (1.f / D_MODEL);
    float rstd = rsqrtf(var + EPS);

    float* orow = out + (size_t)row * D_MODEL;
#pragma unroll
    for (int i = 0; i < 4; i++) {
        int c = tid + i * 256;
        orow[c] = (vals[i] - mu) * rstd * g[c] + be[c];
    }
}

// =======================================================================
// kernel_launch
// input order: x, Wq, bq, Wk, bk, Wv, bv, Wo, bo, W1, b1, W2, b2, g1, be1, g2, be2
// =======================================================================
extern "C" void kernel_launch(void* const* d_in, const int* in_sizes, int n_in,
                              void* d_out, int out_size)
{
    const float* x   = (const float*)d_in[0];
    const float* Wq  = (const float*)d_in[1];
    const float* bq  = (const float*)d_in[2];
    const float* Wk  = (const float*)d_in[3];
    const float* bk  = (const float*)d_in[4];
    const float* Wv  = (const float*)d_in[5];
    const float* bv  = (const float*)d_in[6];
    const float* Wo  = (const float*)d_in[7];
    const float* bo  = (const float*)d_in[8];
    const float* W1  = (const float*)d_in[9];
    const float* b1  = (const float*)d_in[10];
    const float* W2  = (const float*)d_in[11];
    const float* b2  = (const float*)d_in[12];
    const float* g1  = (const float*)d_in[13];
    const float* be1 = (const float*)d_in[14];
    const float* g2  = (const float*)d_in[15];
    const float* be2 = (const float*)d_in[16];
    float* out = (float*)d_out;

    __half *qh, *kh, *vh;
    float *att, *tmp, *h, *ff;
    cudaGetSymbolAddress((void**)&qh,  g_qh);
    cudaGetSymbolAddress((void**)&kh,  g_kh);
    cudaGetSymbolAddress((void**)&vh,  g_vh);
    cudaGetSymbolAddress((void**)&att, g_att);
    cudaGetSymbolAddress((void**)&tmp, g_tmp);
    cudaGetSymbolAddress((void**)&h,   g_h);
    cudaGetSymbolAddress((void**)&ff,  g_ff);

    const dim3 gDxD(D_MODEL / 128, NTOK / 128);   // (8, 32)
    const dim3 gFF1(D_FF / 128,    NTOK / 128);   // (32, 32)

    // QKV projections -> half outputs
    gemm_h<false, true><<<gDxD, 256>>>(x, Wq, bq, qh, NTOK, D_MODEL, D_MODEL);
    gemm_h<false, true><<<gDxD, 256>>>(x, Wk, bk, kh, NTOK, D_MODEL, D_MODEL);
    gemm_h<false, true><<<gDxD, 256>>>(x, Wv, bv, vh, NTOK, D_MODEL, D_MODEL);

    // attention (fp16 HMMA flash)
    flash16<<<dim3(SEQ / 64, BATCH * NHEAD), 128>>>(qh, kh, vh, att);

    // output projection + LN1
    gemm_h<false, false><<<gDxD, 256>>>(att, Wo, bo, tmp, NTOK, D_MODEL, D_MODEL);
    add_ln_kernel<<<NTOK, 256>>>(x, tmp, g1, be1, h);

    // FFN
    gemm_h<true,  false><<<gFF1, 256>>>(h, W1, b1, ff, NTOK, D_FF, D_MODEL);
    gemm_h<false, false><<<gDxD, 256>>>(ff, W2, b2, tmp, NTOK, D_MODEL, D_FF);

    // LN2 -> output
    add_ln_kernel<<<NTOK, 256>>>(h, tmp, g2, be2, out);
}

// round 8
// speedup vs baseline: 7.2318x; 1.2964x over previous
#include <cuda_runtime.h>
#include <cuda_fp16.h>
#include <cuda_bf16.h>
#include <cstdint>

// ---------------- problem constants ----------------
#define D_MODEL 1024
#define NHEAD   16
#define D_HEAD  64
#define D_FF    4096
#define BATCH   2
#define SEQ     2048
#define NTOK    (BATCH * SEQ)       // 4096 tokens
#define EPS     1e-5f

// ---------------- scratch (no allocations allowed) ----------------
__device__ __half g_xh  [NTOK * D_MODEL];
__device__ __half g_Wqh [D_MODEL * D_MODEL];
__device__ __half g_Wkh [D_MODEL * D_MODEL];
__device__ __half g_Wvh [D_MODEL * D_MODEL];
__device__ __half g_Woh [D_MODEL * D_MODEL];
__device__ __half g_W1h [D_FF * D_MODEL];
__device__ __half g_W2h [D_MODEL * D_FF];
__device__ __half g_qh  [NTOK * D_MODEL];
__device__ __half g_kh  [NTOK * D_MODEL];
__device__ __half g_vh  [NTOK * D_MODEL];
__device__ __half g_atth[NTOK * D_MODEL];
__device__ __half g_hh  [NTOK * D_MODEL];
__device__ __half g_ffh [NTOK * D_FF];
__device__ float  g_tmp [NTOK * D_MODEL];   // attn_proj, then ffn2 out
__device__ float  g_h   [NTOK * D_MODEL];   // LN1 output (fp32 residual)

// =======================================================================
// PTX helpers (plain sm_103-compatible: mma.sync / ldmatrix / cp.async)
// =======================================================================
__device__ __forceinline__ uint32_t smem_u32(const void* p) {
    uint32_t a;
    asm("{ .reg .u64 t; cvta.to.shared.u64 t, %1; cvt.u32.u64 %0, t; }"
        : "=r"(a) : "l"(p));
    return a;
}

__device__ __forceinline__ void mma16816(float* d, const uint32_t* a, const uint32_t* b) {
    asm volatile(
        "mma.sync.aligned.m16n8k16.row.col.f32.f16.f16.f32 "
        "{%0,%1,%2,%3}, {%4,%5,%6,%7}, {%8,%9}, {%0,%1,%2,%3};"
        : "+f"(d[0]), "+f"(d[1]), "+f"(d[2]), "+f"(d[3])
        : "r"(a[0]), "r"(a[1]), "r"(a[2]), "r"(a[3]), "r"(b[0]), "r"(b[1]));
}

#define LDMX4(r0, r1, r2, r3, addr)                                         \
    asm volatile("ldmatrix.sync.aligned.m8n8.x4.shared.b16 "                \
                 "{%0,%1,%2,%3}, [%4];"                                     \
                 : "=r"(r0), "=r"(r1), "=r"(r2), "=r"(r3) : "r"(addr))

#define LDMX4T(r0, r1, r2, r3, addr)                                        \
    asm volatile("ldmatrix.sync.aligned.m8n8.x4.trans.shared.b16 "          \
                 "{%0,%1,%2,%3}, [%4];"                                     \
                 : "=r"(r0), "=r"(r1), "=r"(r2), "=r"(r3) : "r"(addr))

#define CP_ASYNC16(saddr, gaddr)                                            \
    asm volatile("cp.async.cg.shared.global [%0], [%1], 16;"                \
                 :: "r"(saddr), "l"(gaddr) : "memory")
#define CP_COMMIT() asm volatile("cp.async.commit_group;" ::: "memory")
#define CP_WAIT(n)  asm volatile("cp.async.wait_group %0;" :: "n"(n) : "memory")

__device__ __forceinline__ uint32_t pack_h2(float lo, float hi) {
    __half2 h = __float22half2_rn(make_float2(lo, hi));
    return *(uint32_t*)&h;
}

// =======================================================================
// fp32 -> fp16 conversion (vectorized)
// =======================================================================
__global__ __launch_bounds__(256)
void f2h_kernel(const float4* __restrict__ in, uint2* __restrict__ out, int n4)
{
    int i = blockIdx.x * blockDim.x + threadIdx.x;
    if (i < n4) {
        float4 v = in[i];
        uint2 o;
        o.x = pack_h2(v.x, v.y);
        o.y = pack_h2(v.z, v.w);
        out[i] = o;
    }
}

// =======================================================================
// fp16 HMMA GEMM, all-half inputs: C[M,N] = A[M,K] @ W[N,K]^T + bias[N]
// CTA 128x128, BK=32, 256 threads = 8 warps (2 M x 4 N), warp tile 64x32.
// 4-stage cp.async pipeline, one __syncthreads per K-tile.
// SMEM rows padded to 40 halfs (80B, 16B-aligned): ldmatrix conflict-free.
// =======================================================================
#define LDSH   40
#define GSTG   4
#define TILE_B (128 * LDSH * 2)           // 10240 B per matrix per stage
#define GSMEM  (2 * GSTG * TILE_B)        // 81920 B

template <bool RELU, bool HALF_OUT>
__global__ __launch_bounds__(256, 2)
void gemm_h(const __half* __restrict__ A, const __half* __restrict__ W,
            const float* __restrict__ bias, void* __restrict__ Cout,
            int M, int N, int K)
{
    extern __shared__ __align__(16) char dsm[];
    const uint32_t smemA = smem_u32(dsm);
    const uint32_t smemW = smemA + GSTG * TILE_B;

    const int tid  = threadIdx.x;
    const int wid  = tid >> 5;
    const int lane = tid & 31;
    const int wm   = wid & 1;
    const int wn   = wid >> 1;
    const int g    = lane >> 2;
    const int t4   = lane & 3;

    const int bm = blockIdx.y * 128;
    const int bn = blockIdx.x * 128;

    float acc[4][4][4];
#pragma unroll
    for (int i = 0; i < 4; i++)
#pragma unroll
        for (int j = 0; j < 4; j++)
#pragma unroll
            for (int c = 0; c < 4; c++) acc[i][j][c] = 0.f;

    // cp.async slots: 512 16B-chunks per matrix per stage; 2 per thread each
    const int crow = (tid * 2) >> 2;          // wrong granularity avoided below
    (void)crow;

#define ISSUE_G(t, s)                                                           \
    do {                                                                        \
        const uint32_t sa = smemA + (s) * TILE_B;                               \
        const uint32_t sw = smemW + (s) * TILE_B;                               \
        _Pragma("unroll")                                                       \
        for (int sl = 0; sl < 2; sl++) {                                        \
            const int idx = tid + sl * 256;          /* 0..511 */               \
            const int row = idx >> 2, c16 = idx & 3;                            \
            CP_ASYNC16(sa + (uint32_t)((row * LDSH + c16 * 8) * 2),             \
                       A + (size_t)(bm + row) * K + (t) * 32 + c16 * 8);        \
        }                                                                       \
        _Pragma("unroll")                                                       \
        for (int sl = 0; sl < 2; sl++) {                                        \
            const int idx = tid + sl * 256;                                     \
            const int row = idx >> 2, c16 = idx & 3;                            \
            CP_ASYNC16(sw + (uint32_t)((row * LDSH + c16 * 8) * 2),             \
                       W + (size_t)(bn + row) * K + (t) * 32 + c16 * 8);        \
        }                                                                       \
    } while (0)

    // ldmatrix byte offsets within one stage
    const int r7   = lane & 7;
    const int rsel = (lane >> 3) & 1;
    const int hsel = lane >> 4;
    const uint32_t offA0 = (uint32_t)((wm * 64 + r7 + rsel * 8) * (LDSH * 2) + hsel * 16);
    const uint32_t offB0 = (uint32_t)((wn * 32 + r7 + hsel * 8) * (LDSH * 2) + rsel * 16);

    const int NT = K / 32;

    // prologue: 3 stages in flight
    ISSUE_G(0, 0); CP_COMMIT();
    ISSUE_G(1, 1); CP_COMMIT();
    ISSUE_G(2, 2); CP_COMMIT();

    for (int t = 0; t < NT; ++t) {
        CP_WAIT(2);                        // stage t landed
        __syncthreads();
        if (t + 3 < NT) ISSUE_G(t + 3, (t + 3) & 3);
        CP_COMMIT();                       // empty group in tail keeps count

        const uint32_t ab = smemA + (uint32_t)((t & 3) * TILE_B) + offA0;
        const uint32_t bb = smemW + (uint32_t)((t & 3) * TILE_B) + offB0;
#pragma unroll
        for (int ks = 0; ks < 2; ks++) {
            uint32_t af[4][4], bf[4][2];
#pragma unroll
            for (int i = 0; i < 4; i++)
                LDMX4(af[i][0], af[i][1], af[i][2], af[i][3],
                      ab + (uint32_t)(i * 16 * LDSH * 2 + ks * 32));
#pragma unroll
            for (int jp = 0; jp < 2; jp++)
                LDMX4(bf[2 * jp][0], bf[2 * jp][1], bf[2 * jp + 1][0], bf[2 * jp + 1][1],
                      bb + (uint32_t)(jp * 16 * LDSH * 2 + ks * 32));
#pragma unroll
            for (int i = 0; i < 4; i++)
#pragma unroll
                for (int j = 0; j < 4; j++)
                    mma16816(acc[i][j], af[i], bf[j]);
        }
    }

    // ---- epilogue ----
#pragma unroll
    for (int j = 0; j < 4; j++) {
        const int col = bn + wn * 32 + j * 8 + t4 * 2;
        const float b0 = bias[col];
        const float b1 = bias[col + 1];
#pragma unroll
        for (int i = 0; i < 4; i++) {
            const int r0 = bm + wm * 64 + i * 16 + g;
            float v00 = acc[i][j][0] + b0, v01 = acc[i][j][1] + b1;
            float v10 = acc[i][j][2] + b0, v11 = acc[i][j][3] + b1;
            if (RELU) {
                v00 = fmaxf(v00, 0.f); v01 = fmaxf(v01, 0.f);
                v10 = fmaxf(v10, 0.f); v11 = fmaxf(v11, 0.f);
            }
            if (HALF_OUT) {
                __half* C = (__half*)Cout;
                *(__half2*)(C + (size_t)r0 * N + col)       = __float22half2_rn(make_float2(v00, v01));
                *(__half2*)(C + (size_t)(r0 + 8) * N + col) = __float22half2_rn(make_float2(v10, v11));
            } else {
                float* C = (float*)Cout;
                *(float2*)(C + (size_t)r0 * N + col)       = make_float2(v00, v01);
                *(float2*)(C + (size_t)(r0 + 8) * N + col) = make_float2(v10, v11);
            }
        }
    }
#undef ISSUE_G
}

// =======================================================================
// fp16 HMMA flash attention. Q pre-scaled by 0.125 (exact in fp16).
// CTA: 128 threads (4 warps), 64 q-rows. K/V 64-key tiles via cp.async
// double buffered. Output: half.
// =======================================================================
#define ATS 72

__global__ __launch_bounds__(128)
void flash16(const __half* __restrict__ Q, const __half* __restrict__ Kb,
             const __half* __restrict__ Vb, __half* __restrict__ O)
{
    __shared__ __half Qs[64 * ATS];
    __shared__ __half Ks[2][64 * ATS];
    __shared__ __half Vs[2][64 * ATS];

    const int tid  = threadIdx.x;
    const int w    = tid >> 5;
    const int lane = tid & 31;
    const int g    = lane >> 2;
    const int t4   = lane & 3;
    const int bh   = blockIdx.y;
    const int b    = bh >> 4;
    const int h    = bh & 15;
    const int q0   = blockIdx.x * 64;
    const int m    = w * 16;

    const size_t base = (size_t)b * SEQ * D_MODEL + (size_t)h * D_HEAD;

    // ---- load Q tile (scaled by 0.125) ----
    const __half2 sc = __float2half2_rn(0.125f);
#pragma unroll
    for (int s = 0; s < 4; s++) {
        int slot = tid + s * 128;
        int row  = slot >> 3;
        int c8   = (slot & 7) * 8;
        uint4 v = *(const uint4*)(Q + base + (size_t)(q0 + row) * D_MODEL + c8);
        __half2* hv = (__half2*)&v;
        hv[0] = __hmul2(hv[0], sc); hv[1] = __hmul2(hv[1], sc);
        hv[2] = __hmul2(hv[2], sc); hv[3] = __hmul2(hv[3], sc);
        *(uint4*)&Qs[row * ATS + c8] = v;
    }
    __syncthreads();

    const int r7   = lane & 7;
    const int rsel = (lane >> 3) & 1;
    const int hsel = lane >> 4;

    uint32_t qf[4][4];
    {
        const uint32_t qb = smem_u32(Qs) +
            (uint32_t)((m + r7 + rsel * 8) * (ATS * 2) + hsel * 16);
#pragma unroll
        for (int ks = 0; ks < 4; ks++)
            LDMX4(qf[ks][0], qf[ks][1], qf[ks][2], qf[ks][3], qb + ks * 32);
    }

    const uint32_t offK0 = (uint32_t)((r7 + hsel * 8) * (ATS * 2) + rsel * 16);
    const uint32_t offV0 = (uint32_t)((rsel * 8 + r7) * (ATS * 2) + hsel * 16);
    const uint32_t kBase[2] = { smem_u32(Ks[0]), smem_u32(Ks[1]) };
    const uint32_t vBase[2] = { smem_u32(Vs[0]), smem_u32(Vs[1]) };

#define ISSUE_TILE(kt, buf)                                                     \
    do {                                                                        \
        _Pragma("unroll")                                                       \
        for (int s = 0; s < 4; s++) {                                           \
            int slot = tid + s * 128;                                           \
            int row  = slot >> 3;                                               \
            int c8   = (slot & 7) * 8;                                          \
            const size_t go = base + (size_t)((kt) * 64 + row) * D_MODEL + c8;  \
            uint32_t so = (uint32_t)((row * ATS + c8) * 2);                     \
            CP_ASYNC16(kBase[buf] + so, Kb + go);                               \
            CP_ASYNC16(vBase[buf] + so, Vb + go);                               \
        }                                                                       \
        CP_COMMIT();                                                            \
    } while (0)

    float o[8][4];
#pragma unroll
    for (int j = 0; j < 8; j++)
#pragma unroll
        for (int c = 0; c < 4; c++) o[j][c] = 0.f;
    float m0 = -1e30f, m1 = -1e30f, l0 = 0.f, l1 = 0.f;

    ISSUE_TILE(0, 0);

    const int NKT = SEQ / 64;
    for (int kt = 0; kt < NKT; ++kt) {
        const int buf = kt & 1;
        if (kt + 1 < NKT) { ISSUE_TILE(kt + 1, buf ^ 1); CP_WAIT(1); }
        else              { CP_WAIT(0); }
        __syncthreads();

        // ---- S = (Q/8) K^T ----
        float s_[8][4];
#pragma unroll
        for (int j = 0; j < 8; j++)
#pragma unroll
            for (int c = 0; c < 4; c++) s_[j][c] = 0.f;

        const uint32_t kb = kBase[buf] + offK0;
#pragma unroll
        for (int ks = 0; ks < 4; ks++) {
            uint32_t bfk[8][2];
#pragma unroll
            for (int jp = 0; jp < 4; jp++)
                LDMX4(bfk[2 * jp][0], bfk[2 * jp][1], bfk[2 * jp + 1][0], bfk[2 * jp + 1][1],
                      kb + (uint32_t)(jp * 16 * ATS * 2 + ks * 32));
#pragma unroll
            for (int j = 0; j < 8; j++)
                mma16816(s_[j], qf[ks], bfk[j]);
        }

        // ---- online softmax ----
        float mx0 = -1e30f, mx1 = -1e30f;
#pragma unroll
        for (int j = 0; j < 8; j++) {
            mx0 = fmaxf(mx0, fmaxf(s_[j][0], s_[j][1]));
            mx1 = fmaxf(mx1, fmaxf(s_[j][2], s_[j][3]));
        }
        mx0 = fmaxf(mx0, __shfl_xor_sync(0xffffffffu, mx0, 1));
        mx0 = fmaxf(mx0, __shfl_xor_sync(0xffffffffu, mx0, 2));
        mx1 = fmaxf(mx1, __shfl_xor_sync(0xffffffffu, mx1, 1));
        mx1 = fmaxf(mx1, __shfl_xor_sync(0xffffffffu, mx1, 2));

        const float nm0 = fmaxf(m0, mx0);
        const float nm1 = fmaxf(m1, mx1);
        const float cr0 = __expf(m0 - nm0);
        const float cr1 = __expf(m1 - nm1);
        m0 = nm0; m1 = nm1;

        float ps0 = 0.f, ps1 = 0.f;
#pragma unroll
        for (int j = 0; j < 8; j++) {
            s_[j][0] = __expf(s_[j][0] - m0);
            s_[j][1] = __expf(s_[j][1] - m0);
            s_[j][2] = __expf(s_[j][2] - m1);
            s_[j][3] = __expf(s_[j][3] - m1);
            ps0 += s_[j][0] + s_[j][1];
            ps1 += s_[j][2] + s_[j][3];
        }
        ps0 += __shfl_xor_sync(0xffffffffu, ps0, 1);
        ps0 += __shfl_xor_sync(0xffffffffu, ps0, 2);
        ps1 += __shfl_xor_sync(0xffffffffu, ps1, 1);
        ps1 += __shfl_xor_sync(0xffffffffu, ps1, 2);
        l0 = l0 * cr0 + ps0;
        l1 = l1 * cr1 + ps1;

#pragma unroll
        for (int j = 0; j < 8; j++) {
            o[j][0] *= cr0; o[j][1] *= cr0;
            o[j][2] *= cr1; o[j][3] *= cr1;
        }

        // ---- O += P V ----
        const uint32_t vb = vBase[buf] + offV0;
#pragma unroll
        for (int ks = 0; ks < 4; ks++) {
            uint32_t pa[4];
            pa[0] = pack_h2(s_[2 * ks][0],     s_[2 * ks][1]);
            pa[1] = pack_h2(s_[2 * ks][2],     s_[2 * ks][3]);
            pa[2] = pack_h2(s_[2 * ks + 1][0], s_[2 * ks + 1][1]);
            pa[3] = pack_h2(s_[2 * ks + 1][2], s_[2 * ks + 1][3]);

            uint32_t bfv[8][2];
#pragma unroll
            for (int jp = 0; jp < 4; jp++)
                LDMX4T(bfv[2 * jp][0], bfv[2 * jp][1], bfv[2 * jp + 1][0], bfv[2 * jp + 1][1],
                       vb + (uint32_t)(ks * 16 * ATS * 2 + jp * 32));
#pragma unroll
            for (int j = 0; j < 8; j++)
                mma16816(o[j], pa, bfv[j]);
        }
        __syncthreads();
    }

    // ---- finalize + store (half) ----
    const float inv0 = 1.f / l0;
    const float inv1 = 1.f / l1;
    const int row0 = q0 + m + g;
    const int row1 = row0 + 8;
#pragma unroll
    for (int j = 0; j < 8; j++) {
        const int col = j * 8 + t4 * 2;
        *(__half2*)(O + base + (size_t)row0 * D_MODEL + col) =
            __float22half2_rn(make_float2(o[j][0] * inv0, o[j][1] * inv0));
        *(__half2*)(O + base + (size_t)row1 * D_MODEL + col) =
            __float22half2_rn(make_float2(o[j][2] * inv1, o[j][3] * inv1));
    }
#undef ISSUE_TILE
}

// =======================================================================
// Fused residual add + LayerNorm; optional extra half output.
// =======================================================================
__device__ __forceinline__ float block_sum(float v, float* red)
{
    for (int o = 16; o; o >>= 1) v += __shfl_down_sync(0xffffffffu, v, o);
    if ((threadIdx.x & 31) == 0) red[threadIdx.x >> 5] = v;
    __syncthreads();
    if (threadIdx.x < 8) {
        v = red[threadIdx.x];
        for (int o = 4; o; o >>= 1) v += __shfl_down_sync(0xffu, v, o);
        if (threadIdx.x == 0) red[0] = v;
    }
    __syncthreads();
    float r = red[0];
    __syncthreads();
    return r;
}

template <bool WRITE_HALF>
__global__ __launch_bounds__(256)
void add_ln_kernel(const float* __restrict__ X,
                   const float* __restrict__ Y,
                   const float* __restrict__ g,
                   const float* __restrict__ be,
                   float* __restrict__ out,
                   __half* __restrict__ outh)
{
    __shared__ float red[8];
    const int row = blockIdx.x;
    const int tid = threadIdx.x;
    const float* xr = X + (size_t)row * D_MODEL;
    const float* yr = Y + (size_t)row * D_MODEL;

    float vals[4];
    float sum = 0.f;
#pragma unroll
    for (int i = 0; i < 4; i++) {
        int c = tid + i * 256;
        vals[i] = xr[c] + yr[c];
        sum += vals[i];
    }
    float mu = block_sum(sum, red) * (1.f / D_MODEL);

    float vsum = 0.f;
#pragma unroll
    for (int i = 0; i < 4; i++) {
        float d = vals[i] - mu;
        vsum += d * d;
    }
    float var = block_sum(vsum, red) * (1.f / D_MODEL);
    float rstd = rsqrtf(var + EPS);

    float* orow = out + (size_t)row * D_MODEL;
    __half* hrow = WRITE_HALF ? outh + (size_t)row * D_MODEL : nullptr;
#pragma unroll
    for (int i = 0; i < 4; i++) {
        int c = tid + i * 256;
        float r = (vals[i] - mu) * rstd * g[c] + be[c];
        orow[c] = r;
        if (WRITE_HALF) hrow[c] = __float2half(r);
    }
}

// =======================================================================
// kernel_launch
// input order: x, Wq, bq, Wk, bk, Wv, bv, Wo, bo, W1, b1, W2, b2, g1, be1, g2, be2
// =======================================================================
extern "C" void kernel_launch(void* const* d_in, const int* in_sizes, int n_in,
                              void* d_out, int out_size)
{
    const float* x   = (const float*)d_in[0];
    const float* Wq  = (const float*)d_in[1];
    const float* bq  = (const float*)d_in[2];
    const float* Wk  = (const float*)d_in[3];
    const float* bk  = (const float*)d_in[4];
    const float* Wv  = (const float*)d_in[5];
    const float* bv  = (const float*)d_in[6];
    const float* Wo  = (const float*)d_in[7];
    const float* bo  = (const float*)d_in[8];
    const float* W1  = (const float*)d_in[9];
    const float* b1  = (const float*)d_in[10];
    const float* W2  = (const float*)d_in[11];
    const float* b2  = (const float*)d_in[12];
    const float* g1  = (const float*)d_in[13];
    const float* be1 = (const float*)d_in[14];
    const float* g2  = (const float*)d_in[15];
    const float* be2 = (const float*)d_in[16];
    float* out = (float*)d_out;

    __half *xh, *Wqh, *Wkh, *Wvh, *Woh, *W1h, *W2h;
    __half *qh, *kh, *vh, *atth, *hh, *ffh;
    float *tmp, *h;
    cudaGetSymbolAddress((void**)&xh,   g_xh);
    cudaGetSymbolAddress((void**)&Wqh,  g_Wqh);
    cudaGetSymbolAddress((void**)&Wkh,  g_Wkh);
    cudaGetSymbolAddress((void**)&Wvh,  g_Wvh);
    cudaGetSymbolAddress((void**)&Woh,  g_Woh);
    cudaGetSymbolAddress((void**)&W1h,  g_W1h);
    cudaGetSymbolAddress((void**)&W2h,  g_W2h);
    cudaGetSymbolAddress((void**)&qh,   g_qh);
    cudaGetSymbolAddress((void**)&kh,   g_kh);
    cudaGetSymbolAddress((void**)&vh,   g_vh);
    cudaGetSymbolAddress((void**)&atth, g_atth);
    cudaGetSymbolAddress((void**)&hh,   g_hh);
    cudaGetSymbolAddress((void**)&ffh,  g_ffh);
    cudaGetSymbolAddress((void**)&tmp,  g_tmp);
    cudaGetSymbolAddress((void**)&h,    g_h);

    cudaFuncSetAttribute(gemm_h<false, true >, cudaFuncAttributeMaxDynamicSharedMemorySize, GSMEM);
    cudaFuncSetAttribute(gemm_h<false, false>, cudaFuncAttributeMaxDynamicSharedMemorySize, GSMEM);
    cudaFuncSetAttribute(gemm_h<true,  true >, cudaFuncAttributeMaxDynamicSharedMemorySize, GSMEM);

    // ---- fp32 -> fp16 conversions ----
    const int NDD = D_MODEL * D_MODEL / 4;   // 262144
    const int NX  = NTOK * D_MODEL / 4;      // 1048576
    const int NW1 = D_FF * D_MODEL / 4;      // 1048576
    f2h_kernel<<<NX  / 256, 256>>>((const float4*)x,  (uint2*)xh,  NX);
    f2h_kernel<<<NDD / 256, 256>>>((const float4*)Wq, (uint2*)Wqh, NDD);
    f2h_kernel<<<NDD / 256, 256>>>((const float4*)Wk, (uint2*)Wkh, NDD);
    f2h_kernel<<<NDD / 256, 256>>>((const float4*)Wv, (uint2*)Wvh, NDD);
    f2h_kernel<<<NDD / 256, 256>>>((const float4*)Wo, (uint2*)Woh, NDD);
    f2h_kernel<<<NW1 / 256, 256>>>((const float4*)W1, (uint2*)W1h, NW1);
    f2h_kernel<<<NW1 / 256, 256>>>((const float4*)W2, (uint2*)W2h, NW1);

    const dim3 gDxD(D_MODEL / 128, NTOK / 128);   // (8, 32)
    const dim3 gFF1(D_FF / 128,    NTOK / 128);   // (32, 32)

    // QKV projections -> half
    gemm_h<false, true><<<gDxD, 256, GSMEM>>>(xh, Wqh, bq, qh, NTOK, D_MODEL, D_MODEL);
    gemm_h<false, true><<<gDxD, 256, GSMEM>>>(xh, Wkh, bk, kh, NTOK, D_MODEL, D_MODEL);
    gemm_h<false, true><<<gDxD, 256, GSMEM>>>(xh, Wvh, bv, vh, NTOK, D_MODEL, D_MODEL);

    // attention -> half
    flash16<<<dim3(SEQ / 64, BATCH * NHEAD), 128>>>(qh, kh, vh, atth);

    // output projection (fp32 out) + LN1 (fp32 + half out)
    gemm_h<false, false><<<gDxD, 256, GSMEM>>>(atth, Woh, bo, tmp, NTOK, D_MODEL, D_MODEL);
    add_ln_kernel<true><<<NTOK, 256>>>(x, tmp, g1, be1, h, hh);

    // FFN
    gemm_h<true,  true ><<<gFF1, 256, GSMEM>>>(hh,  W1h, b1, ffh, NTOK, D_FF, D_MODEL);
    gemm_h<false, false><<<gDxD, 256, GSMEM>>>(ffh, W2h, b2, tmp, NTOK, D_MODEL, D_FF);

    // LN2 -> output
    add_ln_kernel<false><<<NTOK, 256>>>(h, tmp, g2, be2, out, nullptr);
}